// round 3
// baseline (speedup 1.0000x reference)
#include <cuda_runtime.h>
#include <math.h>

// Problem dims (fixed by the reference)
#define T_DIM 8192
#define E_DIM 1024
#define V_DIM 50000

// Scratch (allocation-free rule: use __device__ globals)
__device__ float g_X[(size_t)T_DIM * E_DIM];      // tokens @ W        (32 MB)
__device__ float g_L[(size_t)T_DIM * V_DIM];      // logits vs vocab   (1.64 GB)
__device__ float g_Ld[T_DIM];                     // logits vs default embedding

// ---------------------------------------------------------------------------
// Tiled fp32 GEMMs: BM=BN=128, BK=16, 256 threads, 8x8 microtile
// ---------------------------------------------------------------------------
#define BM 128
#define BN 128
#define BK 16
#define TM 8
#define TN 8
#define SPAD 4

// C[M,N] = A[M,K] * B[N,K]^T   (both operands K-major / row-major)
// M, K must be multiples of 128/16; N guarded.
__global__ void __launch_bounds__(256) gemm_nt_kernel(
    const float* __restrict__ A, const float* __restrict__ B,
    float* __restrict__ C, int M, int N, int K, int ldc)
{
    __shared__ float As[BK][BM + SPAD];
    __shared__ float Bs[BK][BN + SPAD];

    const int tid = threadIdx.x;
    const int bm = blockIdx.y * BM;
    const int bn = blockIdx.x * BN;
    const int tx = tid & 15;
    const int ty = tid >> 4;

    float acc[TM][TN];
#pragma unroll
    for (int i = 0; i < TM; i++)
#pragma unroll
        for (int j = 0; j < TN; j++) acc[i][j] = 0.f;

    for (int k0 = 0; k0 < K; k0 += BK) {
        // A tile: 128 rows x 16 cols = 512 float4, 2 per thread
#pragma unroll
        for (int r = 0; r < 2; r++) {
            int f   = tid + r * 256;
            int row = f >> 2;
            int kq  = (f & 3) * 4;
            float4 v = *(const float4*)&A[(size_t)(bm + row) * K + k0 + kq];
            As[kq + 0][row] = v.x; As[kq + 1][row] = v.y;
            As[kq + 2][row] = v.z; As[kq + 3][row] = v.w;
        }
        // B tile: 128 rows x 16 cols (guard row < N)
#pragma unroll
        for (int r = 0; r < 2; r++) {
            int f   = tid + r * 256;
            int row = f >> 2;
            int kq  = (f & 3) * 4;
            int gn  = bn + row;
            float4 v = make_float4(0.f, 0.f, 0.f, 0.f);
            if (gn < N) v = *(const float4*)&B[(size_t)gn * K + k0 + kq];
            Bs[kq + 0][row] = v.x; Bs[kq + 1][row] = v.y;
            Bs[kq + 2][row] = v.z; Bs[kq + 3][row] = v.w;
        }
        __syncthreads();
#pragma unroll
        for (int kk = 0; kk < BK; kk++) {
            float a[TM], b[TN];
#pragma unroll
            for (int i = 0; i < TM; i++) a[i] = As[kk][ty * TM + i];
#pragma unroll
            for (int j = 0; j < TN; j++) b[j] = Bs[kk][tx * TN + j];
#pragma unroll
            for (int i = 0; i < TM; i++)
#pragma unroll
                for (int j = 0; j < TN; j++) acc[i][j] += a[i] * b[j];
        }
        __syncthreads();
    }

#pragma unroll
    for (int i = 0; i < TM; i++) {
        int gm = bm + ty * TM + i;
#pragma unroll
        for (int j = 0; j < TN; j++) {
            int gn = bn + tx * TN + j;
            if (gn < N) C[(size_t)gm * ldc + gn] = acc[i][j];
        }
    }
}

// C[M,N] = A[M,K] * B[K,N]   (all row-major).  M,N,K clean multiples.
__global__ void __launch_bounds__(256) gemm_nn_kernel(
    const float* __restrict__ A, const float* __restrict__ B,
    float* __restrict__ C, int M, int N, int K)
{
    __shared__ float As[BK][BM + SPAD];
    __shared__ float Bs[BK][BN + SPAD];

    const int tid = threadIdx.x;
    const int bm = blockIdx.y * BM;
    const int bn = blockIdx.x * BN;
    const int tx = tid & 15;
    const int ty = tid >> 4;

    float acc[TM][TN];
#pragma unroll
    for (int i = 0; i < TM; i++)
#pragma unroll
        for (int j = 0; j < TN; j++) acc[i][j] = 0.f;

    for (int k0 = 0; k0 < K; k0 += BK) {
        // A tile (transpose into As)
#pragma unroll
        for (int r = 0; r < 2; r++) {
            int f   = tid + r * 256;
            int row = f >> 2;
            int kq  = (f & 3) * 4;
            float4 v = *(const float4*)&A[(size_t)(bm + row) * K + k0 + kq];
            As[kq + 0][row] = v.x; As[kq + 1][row] = v.y;
            As[kq + 2][row] = v.z; As[kq + 3][row] = v.w;
        }
        // B tile: 16 rows x 128 cols, direct
#pragma unroll
        for (int r = 0; r < 2; r++) {
            int f  = tid + r * 256;
            int kr = f >> 5;           // 0..15
            int nq = (f & 31) * 4;     // 0..124
            float4 v = *(const float4*)&B[(size_t)(k0 + kr) * N + bn + nq];
            Bs[kr][nq + 0] = v.x; Bs[kr][nq + 1] = v.y;
            Bs[kr][nq + 2] = v.z; Bs[kr][nq + 3] = v.w;
        }
        __syncthreads();
#pragma unroll
        for (int kk = 0; kk < BK; kk++) {
            float a[TM], b[TN];
#pragma unroll
            for (int i = 0; i < TM; i++) a[i] = As[kk][ty * TM + i];
#pragma unroll
            for (int j = 0; j < TN; j++) b[j] = Bs[kk][tx * TN + j];
#pragma unroll
            for (int i = 0; i < TM; i++)
#pragma unroll
                for (int j = 0; j < TN; j++) acc[i][j] += a[i] * b[j];
        }
        __syncthreads();
    }

#pragma unroll
    for (int i = 0; i < TM; i++) {
        int gm = bm + ty * TM + i;
#pragma unroll
        for (int j = 0; j < TN; j++) {
            C[(size_t)gm * N + bn + tx * TN + j] = acc[i][j];
        }
    }
}

// ---------------------------------------------------------------------------
// Ld[t] = dot(X[t,:], default_embedding)   (one warp per row)
// ---------------------------------------------------------------------------
__global__ void __launch_bounds__(256) dot_default_kernel(
    const float* __restrict__ X, const float* __restrict__ d,
    float* __restrict__ Ld)
{
    int w    = threadIdx.x >> 5;
    int lane = threadIdx.x & 31;
    int t    = blockIdx.x * 8 + w;
    const float4* xr = (const float4*)(X + (size_t)t * E_DIM);
    const float4* dr = (const float4*)d;
    float s = 0.f;
    for (int q = lane; q < E_DIM / 4; q += 32) {
        float4 a = xr[q], b = dr[q];
        s += a.x * b.x + a.y * b.y + a.z * b.z + a.w * b.w;
    }
#pragma unroll
    for (int o = 16; o; o >>= 1) s += __shfl_xor_sync(0xffffffffu, s, o);
    if (lane == 0) Ld[t] = s;
}

// ---------------------------------------------------------------------------
// Per-row softmax + sparse gather: out[t] = w_def*tokens[t] + sum w_v*vocab[v]
// Only weights > THR contribute (softmax is extremely peaked: logit sigma~32).
// ---------------------------------------------------------------------------
#define GCHUNK 2048
#define WTHR   1e-8f

__global__ void __launch_bounds__(256) softmax_gather_kernel(
    const float* __restrict__ L, const float* __restrict__ Ld,
    const float* __restrict__ tokens, const float* __restrict__ vocab,
    float* __restrict__ out)
{
    const int t   = blockIdx.x;
    const int tid = threadIdx.x;
    const float* row = L + (size_t)t * V_DIM;

    __shared__ float red[256];
    __shared__ int   s_idx[GCHUNK];
    __shared__ float s_w[GCHUNK];
    __shared__ int   s_cnt;

    const float ld = Ld[t];

    // ---- row max (includes default logit) ----
    float m = ld;
    for (int i = tid; i < V_DIM; i += 256) m = fmaxf(m, row[i]);
    red[tid] = m; __syncthreads();
    for (int s = 128; s > 0; s >>= 1) {
        if (tid < s) red[tid] = fmaxf(red[tid], red[tid + s]);
        __syncthreads();
    }
    m = red[0]; __syncthreads();

    // ---- row sum of exp ----
    float z = (tid == 0) ? __expf(ld - m) : 0.f;
    for (int i = tid; i < V_DIM; i += 256) z += __expf(row[i] - m);
    red[tid] = z; __syncthreads();
    for (int s = 128; s > 0; s >>= 1) {
        if (tid < s) red[tid] += red[tid + s];
        __syncthreads();
    }
    const float Z   = red[0];
    const float inv = 1.0f / Z;
    __syncthreads();

    // weight > WTHR  <=>  logit > m + log(WTHR * Z)
    const float cutoff = m + logf(WTHR) + logf(Z);

    // accumulator: thread owns 4 output columns; seed with default-key term
    const float wdef = __expf(ld - m) * inv;
    float4 tk  = ((const float4*)(tokens + (size_t)t * E_DIM))[tid];
    float4 acc = make_float4(wdef * tk.x, wdef * tk.y, wdef * tk.z, wdef * tk.w);

    // ---- scan logits in chunks, gather significant vocab rows ----
    for (int base = 0; base < V_DIM; base += GCHUNK) {
        if (tid == 0) s_cnt = 0;
        __syncthreads();
        int end = min(base + GCHUNK, V_DIM);
        for (int i = base + tid; i < end; i += 256) {
            float l = row[i];
            if (l > cutoff) {
                int p = atomicAdd(&s_cnt, 1);
                s_idx[p] = i;
                s_w[p]   = __expf(l - m) * inv;
            }
        }
        __syncthreads();
        int cnt = s_cnt;
        for (int p = 0; p < cnt; p++) {
            float w = s_w[p];
            float4 v = ((const float4*)(vocab + (size_t)s_idx[p] * E_DIM))[tid];
            acc.x += w * v.x; acc.y += w * v.y;
            acc.z += w * v.z; acc.w += w * v.w;
        }
        __syncthreads();
    }

    ((float4*)out)[(size_t)t * (E_DIM / 4) + tid] = acc;
}

// ---------------------------------------------------------------------------
// Launch
// ---------------------------------------------------------------------------
extern "C" void kernel_launch(void* const* d_in, const int* in_sizes, int n_in,
                              void* d_out, int out_size)
{
    const float* tokens = (const float*)d_in[0];   // [T, E]
    const float* vocab  = (const float*)d_in[1];   // [V, E]
    const float* weight = (const float*)d_in[2];   // [E, E]
    const float* dEmb   = (const float*)d_in[3];   // [E]
    float* out = (float*)d_out;                    // [T, E]

    float *X, *L, *Ld;
    cudaGetSymbolAddress((void**)&X,  g_X);
    cudaGetSymbolAddress((void**)&L,  g_L);
    cudaGetSymbolAddress((void**)&Ld, g_Ld);

    // 1) X = tokens @ W      [8192,1024] x [1024,1024]
    gemm_nn_kernel<<<dim3(E_DIM / BN, T_DIM / BM), 256>>>(
        tokens, weight, X, T_DIM, E_DIM, E_DIM);

    // 2) L = X @ vocab^T     [8192,1024] x [50000,1024]^T
    gemm_nt_kernel<<<dim3((V_DIM + BN - 1) / BN, T_DIM / BM), 256>>>(
        X, vocab, L, T_DIM, V_DIM, E_DIM, V_DIM);

    // 3) Ld = X @ default_embedding
    dot_default_kernel<<<T_DIM / 8, 256>>>(X, dEmb, Ld);

    // 4) softmax + sparse gather -> out
    softmax_gather_kernel<<<T_DIM, 256>>>(L, Ld, tokens, vocab, out);
}

// round 4
// speedup vs baseline: 1.0002x; 1.0002x over previous
#include <cuda_runtime.h>
#include <math.h>

// Problem dims (fixed by the reference)
#define T_DIM 8192
#define E_DIM 1024
#define V_DIM 50000

// Scratch (allocation-free rule: use __device__ globals)
__device__ float g_X[(size_t)T_DIM * E_DIM];      // tokens @ W        (32 MB)
__device__ float g_L[(size_t)T_DIM * V_DIM];      // logits vs vocab   (1.64 GB)
__device__ float g_Ld[T_DIM];                     // logits vs default embedding

// ---------------------------------------------------------------------------
// Tiled fp32 GEMMs: BM=BN=128, BK=16, 256 threads, 8x8 microtile
// ---------------------------------------------------------------------------
#define BM 128
#define BN 128
#define BK 16
#define TM 8
#define TN 8
#define SPAD 4

// C[M,N] = A[M,K] * B[N,K]^T   (both operands K-major / row-major)
// M, K must be multiples of 128/16; N guarded.
__global__ void __launch_bounds__(256) gemm_nt_kernel(
    const float* __restrict__ A, const float* __restrict__ B,
    float* __restrict__ C, int M, int N, int K, int ldc)
{
    __shared__ float As[BK][BM + SPAD];
    __shared__ float Bs[BK][BN + SPAD];

    const int tid = threadIdx.x;
    const int bm = blockIdx.y * BM;
    const int bn = blockIdx.x * BN;
    const int tx = tid & 15;
    const int ty = tid >> 4;

    float acc[TM][TN];
#pragma unroll
    for (int i = 0; i < TM; i++)
#pragma unroll
        for (int j = 0; j < TN; j++) acc[i][j] = 0.f;

    for (int k0 = 0; k0 < K; k0 += BK) {
        // A tile: 128 rows x 16 cols = 512 float4, 2 per thread
#pragma unroll
        for (int r = 0; r < 2; r++) {
            int f   = tid + r * 256;
            int row = f >> 2;
            int kq  = (f & 3) * 4;
            float4 v = *(const float4*)&A[(size_t)(bm + row) * K + k0 + kq];
            As[kq + 0][row] = v.x; As[kq + 1][row] = v.y;
            As[kq + 2][row] = v.z; As[kq + 3][row] = v.w;
        }
        // B tile: 128 rows x 16 cols (guard row < N)
#pragma unroll
        for (int r = 0; r < 2; r++) {
            int f   = tid + r * 256;
            int row = f >> 2;
            int kq  = (f & 3) * 4;
            int gn  = bn + row;
            float4 v = make_float4(0.f, 0.f, 0.f, 0.f);
            if (gn < N) v = *(const float4*)&B[(size_t)gn * K + k0 + kq];
            Bs[kq + 0][row] = v.x; Bs[kq + 1][row] = v.y;
            Bs[kq + 2][row] = v.z; Bs[kq + 3][row] = v.w;
        }
        __syncthreads();
#pragma unroll
        for (int kk = 0; kk < BK; kk++) {
            float a[TM], b[TN];
#pragma unroll
            for (int i = 0; i < TM; i++) a[i] = As[kk][ty * TM + i];
#pragma unroll
            for (int j = 0; j < TN; j++) b[j] = Bs[kk][tx * TN + j];
#pragma unroll
            for (int i = 0; i < TM; i++)
#pragma unroll
                for (int j = 0; j < TN; j++) acc[i][j] += a[i] * b[j];
        }
        __syncthreads();
    }

#pragma unroll
    for (int i = 0; i < TM; i++) {
        int gm = bm + ty * TM + i;
#pragma unroll
        for (int j = 0; j < TN; j++) {
            int gn = bn + tx * TN + j;
            if (gn < N) C[(size_t)gm * ldc + gn] = acc[i][j];
        }
    }
}

// C[M,N] = A[M,K] * B[K,N]   (all row-major).  M,N,K clean multiples.
__global__ void __launch_bounds__(256) gemm_nn_kernel(
    const float* __restrict__ A, const float* __restrict__ B,
    float* __restrict__ C, int M, int N, int K)
{
    __shared__ float As[BK][BM + SPAD];
    __shared__ float Bs[BK][BN + SPAD];

    const int tid = threadIdx.x;
    const int bm = blockIdx.y * BM;
    const int bn = blockIdx.x * BN;
    const int tx = tid & 15;
    const int ty = tid >> 4;

    float acc[TM][TN];
#pragma unroll
    for (int i = 0; i < TM; i++)
#pragma unroll
        for (int j = 0; j < TN; j++) acc[i][j] = 0.f;

    for (int k0 = 0; k0 < K; k0 += BK) {
        // A tile (transpose into As)
#pragma unroll
        for (int r = 0; r < 2; r++) {
            int f   = tid + r * 256;
            int row = f >> 2;
            int kq  = (f & 3) * 4;
            float4 v = *(const float4*)&A[(size_t)(bm + row) * K + k0 + kq];
            As[kq + 0][row] = v.x; As[kq + 1][row] = v.y;
            As[kq + 2][row] = v.z; As[kq + 3][row] = v.w;
        }
        // B tile: 16 rows x 128 cols, direct
#pragma unroll
        for (int r = 0; r < 2; r++) {
            int f  = tid + r * 256;
            int kr = f >> 5;           // 0..15
            int nq = (f & 31) * 4;     // 0..124
            float4 v = *(const float4*)&B[(size_t)(k0 + kr) * N + bn + nq];
            Bs[kr][nq + 0] = v.x; Bs[kr][nq + 1] = v.y;
            Bs[kr][nq + 2] = v.z; Bs[kr][nq + 3] = v.w;
        }
        __syncthreads();
#pragma unroll
        for (int kk = 0; kk < BK; kk++) {
            float a[TM], b[TN];
#pragma unroll
            for (int i = 0; i < TM; i++) a[i] = As[kk][ty * TM + i];
#pragma unroll
            for (int j = 0; j < TN; j++) b[j] = Bs[kk][tx * TN + j];
#pragma unroll
            for (int i = 0; i < TM; i++)
#pragma unroll
                for (int j = 0; j < TN; j++) acc[i][j] += a[i] * b[j];
        }
        __syncthreads();
    }

#pragma unroll
    for (int i = 0; i < TM; i++) {
        int gm = bm + ty * TM + i;
#pragma unroll
        for (int j = 0; j < TN; j++) {
            C[(size_t)gm * N + bn + tx * TN + j] = acc[i][j];
        }
    }
}

// ---------------------------------------------------------------------------
// Ld[t] = dot(X[t,:], default_embedding)   (one warp per row)
// ---------------------------------------------------------------------------
__global__ void __launch_bounds__(256) dot_default_kernel(
    const float* __restrict__ X, const float* __restrict__ d,
    float* __restrict__ Ld)
{
    int w    = threadIdx.x >> 5;
    int lane = threadIdx.x & 31;
    int t    = blockIdx.x * 8 + w;
    const float4* xr = (const float4*)(X + (size_t)t * E_DIM);
    const float4* dr = (const float4*)d;
    float s = 0.f;
    for (int q = lane; q < E_DIM / 4; q += 32) {
        float4 a = xr[q], b = dr[q];
        s += a.x * b.x + a.y * b.y + a.z * b.z + a.w * b.w;
    }
#pragma unroll
    for (int o = 16; o; o >>= 1) s += __shfl_xor_sync(0xffffffffu, s, o);
    if (lane == 0) Ld[t] = s;
}

// ---------------------------------------------------------------------------
// Per-row softmax + sparse gather: out[t] = w_def*tokens[t] + sum w_v*vocab[v]
// Only weights > THR contribute (softmax is extremely peaked: logit sigma~32).
// ---------------------------------------------------------------------------
#define GCHUNK 2048
#define WTHR   1e-8f

__global__ void __launch_bounds__(256) softmax_gather_kernel(
    const float* __restrict__ L, const float* __restrict__ Ld,
    const float* __restrict__ tokens, const float* __restrict__ vocab,
    float* __restrict__ out)
{
    const int t   = blockIdx.x;
    const int tid = threadIdx.x;
    const float* row = L + (size_t)t * V_DIM;

    __shared__ float red[256];
    __shared__ int   s_idx[GCHUNK];
    __shared__ float s_w[GCHUNK];
    __shared__ int   s_cnt;

    const float ld = Ld[t];

    // ---- row max (includes default logit) ----
    float m = ld;
    for (int i = tid; i < V_DIM; i += 256) m = fmaxf(m, row[i]);
    red[tid] = m; __syncthreads();
    for (int s = 128; s > 0; s >>= 1) {
        if (tid < s) red[tid] = fmaxf(red[tid], red[tid + s]);
        __syncthreads();
    }
    m = red[0]; __syncthreads();

    // ---- row sum of exp ----
    float z = (tid == 0) ? __expf(ld - m) : 0.f;
    for (int i = tid; i < V_DIM; i += 256) z += __expf(row[i] - m);
    red[tid] = z; __syncthreads();
    for (int s = 128; s > 0; s >>= 1) {
        if (tid < s) red[tid] += red[tid + s];
        __syncthreads();
    }
    const float Z   = red[0];
    const float inv = 1.0f / Z;
    __syncthreads();

    // weight > WTHR  <=>  logit > m + log(WTHR * Z)
    const float cutoff = m + logf(WTHR) + logf(Z);

    // accumulator: thread owns 4 output columns; seed with default-key term
    const float wdef = __expf(ld - m) * inv;
    float4 tk  = ((const float4*)(tokens + (size_t)t * E_DIM))[tid];
    float4 acc = make_float4(wdef * tk.x, wdef * tk.y, wdef * tk.z, wdef * tk.w);

    // ---- scan logits in chunks, gather significant vocab rows ----
    for (int base = 0; base < V_DIM; base += GCHUNK) {
        if (tid == 0) s_cnt = 0;
        __syncthreads();
        int end = min(base + GCHUNK, V_DIM);
        for (int i = base + tid; i < end; i += 256) {
            float l = row[i];
            if (l > cutoff) {
                int p = atomicAdd(&s_cnt, 1);
                s_idx[p] = i;
                s_w[p]   = __expf(l - m) * inv;
            }
        }
        __syncthreads();
        int cnt = s_cnt;
        for (int p = 0; p < cnt; p++) {
            float w = s_w[p];
            float4 v = ((const float4*)(vocab + (size_t)s_idx[p] * E_DIM))[tid];
            acc.x += w * v.x; acc.y += w * v.y;
            acc.z += w * v.z; acc.w += w * v.w;
        }
        __syncthreads();
    }

    ((float4*)out)[(size_t)t * (E_DIM / 4) + tid] = acc;
}

// ---------------------------------------------------------------------------
// Launch
// ---------------------------------------------------------------------------
extern "C" void kernel_launch(void* const* d_in, const int* in_sizes, int n_in,
                              void* d_out, int out_size)
{
    const float* tokens = (const float*)d_in[0];   // [T, E]
    const float* vocab  = (const float*)d_in[1];   // [V, E]
    const float* weight = (const float*)d_in[2];   // [E, E]
    const float* dEmb   = (const float*)d_in[3];   // [E]
    float* out = (float*)d_out;                    // [T, E]

    float *X, *L, *Ld;
    cudaGetSymbolAddress((void**)&X,  g_X);
    cudaGetSymbolAddress((void**)&L,  g_L);
    cudaGetSymbolAddress((void**)&Ld, g_Ld);

    // 1) X = tokens @ W      [8192,1024] x [1024,1024]
    gemm_nn_kernel<<<dim3(E_DIM / BN, T_DIM / BM), 256>>>(
        tokens, weight, X, T_DIM, E_DIM, E_DIM);

    // 2) L = X @ vocab^T     [8192,1024] x [50000,1024]^T
    gemm_nt_kernel<<<dim3((V_DIM + BN - 1) / BN, T_DIM / BM), 256>>>(
        X, vocab, L, T_DIM, V_DIM, E_DIM, V_DIM);

    // 3) Ld = X @ default_embedding
    dot_default_kernel<<<T_DIM / 8, 256>>>(X, dEmb, Ld);

    // 4) softmax + sparse gather -> out
    softmax_gather_kernel<<<T_DIM, 256>>>(L, Ld, tokens, vocab, out);
}

// round 6
// speedup vs baseline: 2.9069x; 2.9064x over previous
#include <cuda_runtime.h>
#include <cuda_bf16.h>
#include <math.h>
#include <stdint.h>

// Problem dims (fixed by the reference)
#define T_DIM 8192
#define E_DIM 1024
#define V_DIM 50000
#define K3    (3 * E_DIM)          // 3072: [hi|hi|lo] x [hi|lo|hi] K-concat

// Scratch (allocation-free rule: __device__ globals)
__device__ float g_X[(size_t)T_DIM * E_DIM];                  // tokens @ W (32 MB)
__device__ float g_L[(size_t)T_DIM * V_DIM];                  // logits (1.64 GB)
__device__ float g_Ld[T_DIM];
__device__ __nv_bfloat16 g_Xcat[(size_t)T_DIM * K3];          // 50 MB
__device__ __nv_bfloat16 g_Vcat[(size_t)V_DIM * K3];          // 307 MB

// ===========================================================================
// PTX helpers (baseline sm_80+ features only: compile clean for compute_103)
// ===========================================================================
__device__ __forceinline__ uint32_t smem_u32(const void* p) {
    uint32_t a;
    asm("{ .reg .u64 t; cvta.to.shared.u64 t, %1; cvt.u32.u64 %0, t; }"
        : "=r"(a) : "l"(p));
    return a;
}

__device__ __forceinline__ void cp16(uint32_t dst, const void* src, uint32_t sz) {
    asm volatile("cp.async.cg.shared.global [%0], [%1], 16, %2;"
                 :: "r"(dst), "l"(src), "r"(sz) : "memory");
}

__device__ __forceinline__ void ldsm_x4(uint32_t& r0, uint32_t& r1,
                                        uint32_t& r2, uint32_t& r3, uint32_t addr) {
    asm volatile("ldmatrix.sync.aligned.m8n8.x4.shared.b16 {%0,%1,%2,%3}, [%4];"
                 : "=r"(r0), "=r"(r1), "=r"(r2), "=r"(r3) : "r"(addr));
}

__device__ __forceinline__ void mma_bf16(float* c, const uint32_t* a,
                                         uint32_t b0, uint32_t b1) {
    asm volatile(
        "mma.sync.aligned.m16n8k16.row.col.f32.bf16.bf16.f32 "
        "{%0,%1,%2,%3}, {%4,%5,%6,%7}, {%8,%9}, {%0,%1,%2,%3};"
        : "+f"(c[0]), "+f"(c[1]), "+f"(c[2]), "+f"(c[3])
        : "r"(a[0]), "r"(a[1]), "r"(a[2]), "r"(a[3]), "r"(b0), "r"(b1));
}

__device__ __forceinline__ uint32_t swz(uint32_t o) { return o ^ ((o >> 3) & 0x70); }

// ===========================================================================
// fp32 -> bf16 hi/lo K-concat split.
// dst row length = 3E.  hi goes to the two segments != lo_seg, lo to lo_seg.
//   X uses lo_seg=2 -> [hi|hi|lo];  V uses lo_seg=1 -> [hi|lo|hi]
// ===========================================================================
__global__ void __launch_bounds__(256) split_cat_kernel(
    const float* __restrict__ src, __nv_bfloat16* __restrict__ dst,
    int n4, int lo_seg)
{
    int i = blockIdx.x * 256 + threadIdx.x;
    if (i >= n4) return;
    int row = i >> 8;              // E/4 = 256 float4 per row
    int c4  = i & 255;
    float4 v = ((const float4*)src)[i];

    __nv_bfloat16 h0 = __float2bfloat16(v.x), h1 = __float2bfloat16(v.y);
    __nv_bfloat16 h2 = __float2bfloat16(v.z), h3 = __float2bfloat16(v.w);
    __nv_bfloat162 hA(h0, h1), hB(h2, h3);
    __nv_bfloat162 lA(__float2bfloat16(v.x - __bfloat162float(h0)),
                      __float2bfloat16(v.y - __bfloat162float(h1)));
    __nv_bfloat162 lB(__float2bfloat16(v.z - __bfloat162float(h2)),
                      __float2bfloat16(v.w - __bfloat162float(h3)));

    __nv_bfloat162* d = (__nv_bfloat162*)(dst + (size_t)row * K3);
#pragma unroll
    for (int seg = 0; seg < 3; ++seg) {
        __nv_bfloat162* p = d + seg * (E_DIM / 2) + c4 * 2;
        if (seg == lo_seg) { p[0] = lA; p[1] = lB; }
        else               { p[0] = hA; p[1] = hB; }
    }
}

// ===========================================================================
// bf16 mma.sync GEMM:  C[T,V] = Xcat[T,K3] * Vcat[V,K3]^T
// CTA 128x128, BK=64, 8 warps (2x4) each 64x32, double-buffered cp.async
// ===========================================================================
#define GBK 64
#define KITERS (K3 / GBK)                 // 48
#define STAGE_B 32768                     // A 16K + B 16K per stage
#define GEMM_SMEM (2 * STAGE_B)

__global__ void __launch_bounds__(256, 2) mma_gemm_kernel(
    const __nv_bfloat16* __restrict__ A, const __nv_bfloat16* __restrict__ B,
    float* __restrict__ C)
{
    extern __shared__ __align__(1024) char sm[];
    const uint32_t sbase = smem_u32(sm);
    const int tid  = threadIdx.x;
    const int lane = tid & 31;
    const int wid  = tid >> 5;
    const int bm = blockIdx.x * 128;
    const int bn = blockIdx.y * 128;
    const int wm = (wid >> 2) * 64;       // warp m-offset within tile
    const int wn = (wid & 3) * 32;        // warp n-offset

    float acc[4][4][4];
#pragma unroll
    for (int mt = 0; mt < 4; mt++)
#pragma unroll
        for (int nt = 0; nt < 4; nt++)
#pragma unroll
            for (int r = 0; r < 4; r++) acc[mt][nt][r] = 0.f;

    auto load_stage = [&](int s, int k0) {
        uint32_t sa = sbase + s * STAGE_B;
#pragma unroll
        for (int r = 0; r < 4; ++r) {               // A: 128 rows x 128B
            int f = tid + r * 256;
            int row = f >> 3, q = f & 7;
            uint32_t so = swz((uint32_t)(row * 128 + q * 16));
            cp16(sa + so,
                 (const char*)(A + (size_t)(bm + row) * K3 + k0) + q * 16, 16u);
        }
#pragma unroll
        for (int r = 0; r < 4; ++r) {               // B: 128 rows x 128B (guard V)
            int f = tid + r * 256;
            int row = f >> 3, q = f & 7;
            int vr = bn + row;
            uint32_t so = swz((uint32_t)(row * 128 + q * 16));
            const char* src = (const char*)(
                B + (size_t)(vr < V_DIM ? vr : V_DIM - 1) * K3 + k0) + q * 16;
            cp16(sa + 16384 + so, src, vr < V_DIM ? 16u : 0u);
        }
    };

    load_stage(0, 0);
    asm volatile("cp.async.commit_group;" ::: "memory");

    for (int it = 0; it < KITERS; ++it) {
        if (it + 1 < KITERS) load_stage((it + 1) & 1, (it + 1) * GBK);
        asm volatile("cp.async.commit_group;" ::: "memory");
        asm volatile("cp.async.wait_group 1;" ::: "memory");
        __syncthreads();

        uint32_t sa = sbase + (it & 1) * STAGE_B;
        uint32_t sb = sa + 16384;
#pragma unroll
        for (int ks = 0; ks < 4; ++ks) {            // K=16 per mma
            uint32_t a[4][4], b[2][4];
#pragma unroll
            for (int mt = 0; mt < 4; ++mt) {
                int row  = wm + mt * 16 + (lane & 15);
                int colb = ks * 32 + ((lane >> 4) << 4);
                ldsm_x4(a[mt][0], a[mt][1], a[mt][2], a[mt][3],
                        sa + swz((uint32_t)(row * 128 + colb)));
            }
#pragma unroll
            for (int np = 0; np < 2; ++np) {        // two n16 groups
                int nrow = wn + np * 16 + ((lane >> 4) << 3) + (lane & 7);
                int colb = ks * 32 + (((lane >> 3) & 1) << 4);
                ldsm_x4(b[np][0], b[np][1], b[np][2], b[np][3],
                        sb + swz((uint32_t)(nrow * 128 + colb)));
            }
#pragma unroll
            for (int mt = 0; mt < 4; ++mt)
#pragma unroll
                for (int nt = 0; nt < 4; ++nt)
                    mma_bf16(acc[mt][nt], a[mt],
                             b[nt >> 1][(nt & 1) * 2], b[nt >> 1][(nt & 1) * 2 + 1]);
        }
        __syncthreads();
    }

    // Epilogue: c0,c1 -> (row, col..col+1); c2,c3 -> (row+8, ..)
#pragma unroll
    for (int mt = 0; mt < 4; ++mt) {
        int row = bm + wm + mt * 16 + (lane >> 2);
        float* r0 = C + (size_t)row * V_DIM;
        float* r1 = C + (size_t)(row + 8) * V_DIM;
#pragma unroll
        for (int nt = 0; nt < 4; ++nt) {
            int col = bn + wn + nt * 8 + ((lane & 3) << 1);
            if (col < V_DIM) {
                *(float2*)(r0 + col) = make_float2(acc[mt][nt][0], acc[mt][nt][1]);
                *(float2*)(r1 + col) = make_float2(acc[mt][nt][2], acc[mt][nt][3]);
            }
        }
    }
}

// ===========================================================================
// fp32 NN GEMM for X = tokens @ W  (small: 17 GF)
// ===========================================================================
#define BM 128
#define BN 128
#define BK 16
#define TM 8
#define TN 8
#define SPAD 4

__global__ void __launch_bounds__(256) gemm_nn_kernel(
    const float* __restrict__ A, const float* __restrict__ B,
    float* __restrict__ C, int M, int N, int K)
{
    __shared__ float As[BK][BM + SPAD];
    __shared__ float Bs[BK][BN + SPAD];
    const int tid = threadIdx.x;
    const int bm = blockIdx.y * BM;
    const int bn = blockIdx.x * BN;
    const int tx = tid & 15;
    const int ty = tid >> 4;

    float acc[TM][TN];
#pragma unroll
    for (int i = 0; i < TM; i++)
#pragma unroll
        for (int j = 0; j < TN; j++) acc[i][j] = 0.f;

    for (int k0 = 0; k0 < K; k0 += BK) {
#pragma unroll
        for (int r = 0; r < 2; r++) {
            int f = tid + r * 256;
            int row = f >> 2;
            int kq = (f & 3) * 4;
            float4 v = *(const float4*)&A[(size_t)(bm + row) * K + k0 + kq];
            As[kq + 0][row] = v.x; As[kq + 1][row] = v.y;
            As[kq + 2][row] = v.z; As[kq + 3][row] = v.w;
        }
#pragma unroll
        for (int r = 0; r < 2; r++) {
            int f = tid + r * 256;
            int kr = f >> 5;
            int nq = (f & 31) * 4;
            float4 v = *(const float4*)&B[(size_t)(k0 + kr) * N + bn + nq];
            Bs[kr][nq + 0] = v.x; Bs[kr][nq + 1] = v.y;
            Bs[kr][nq + 2] = v.z; Bs[kr][nq + 3] = v.w;
        }
        __syncthreads();
#pragma unroll
        for (int kk = 0; kk < BK; kk++) {
            float a[TM], b[TN];
#pragma unroll
            for (int i = 0; i < TM; i++) a[i] = As[kk][ty * TM + i];
#pragma unroll
            for (int j = 0; j < TN; j++) b[j] = Bs[kk][tx * TN + j];
#pragma unroll
            for (int i = 0; i < TM; i++)
#pragma unroll
                for (int j = 0; j < TN; j++) acc[i][j] += a[i] * b[j];
        }
        __syncthreads();
    }
#pragma unroll
    for (int i = 0; i < TM; i++) {
        int gm = bm + ty * TM + i;
#pragma unroll
        for (int j = 0; j < TN; j++)
            C[(size_t)gm * N + bn + tx * TN + j] = acc[i][j];
    }
}

// ===========================================================================
// Ld[t] = dot(X[t,:], default_embedding)
// ===========================================================================
__global__ void __launch_bounds__(256) dot_default_kernel(
    const float* __restrict__ X, const float* __restrict__ d,
    float* __restrict__ Ld)
{
    int w = threadIdx.x >> 5;
    int lane = threadIdx.x & 31;
    int t = blockIdx.x * 8 + w;
    const float4* xr = (const float4*)(X + (size_t)t * E_DIM);
    const float4* dr = (const float4*)d;
    float s = 0.f;
    for (int q = lane; q < E_DIM / 4; q += 32) {
        float4 a = xr[q], b = dr[q];
        s += a.x * b.x + a.y * b.y + a.z * b.z + a.w * b.w;
    }
#pragma unroll
    for (int o = 16; o; o >>= 1) s += __shfl_xor_sync(0xffffffffu, s, o);
    if (lane == 0) Ld[t] = s;
}

// ===========================================================================
// Softmax (single-pass online max+sum) + sparse gather
// ===========================================================================
#define GCHUNK 2048
#define WTHR   1e-8f

__global__ void __launch_bounds__(256) softmax_gather_kernel(
    const float* __restrict__ L, const float* __restrict__ Ld,
    const float* __restrict__ tokens, const float* __restrict__ vocab,
    float* __restrict__ out)
{
    const int t = blockIdx.x;
    const int tid = threadIdx.x;
    const float* row = L + (size_t)t * V_DIM;

    __shared__ float rm[256], rz[256];
    __shared__ int s_idx[GCHUNK];
    __shared__ float s_w[GCHUNK];
    __shared__ int s_cnt;

    const float ld = Ld[t];

    float m = -3.0e38f, z = 0.f;
    for (int i = tid; i < V_DIM; i += 256) {
        float l = row[i];
        if (l > m) { z = z * __expf(m - l) + 1.f; m = l; }
        else z += __expf(l - m);
    }
    if (tid == 0) {
        if (ld > m) { z = z * __expf(m - ld) + 1.f; m = ld; }
        else z += __expf(ld - m);
    }
    rm[tid] = m; rz[tid] = z; __syncthreads();
    for (int s = 128; s > 0; s >>= 1) {
        if (tid < s) {
            float m2 = rm[tid + s], z2 = rz[tid + s];
            float M = fmaxf(rm[tid], m2);
            rz[tid] = rz[tid] * __expf(rm[tid] - M) + z2 * __expf(m2 - M);
            rm[tid] = M;
        }
        __syncthreads();
    }
    const float M = rm[0];
    const float Z = rz[0];
    const float inv = 1.0f / Z;
    __syncthreads();

    const float cutoff = M + logf(WTHR) + logf(Z);

    const float wdef = __expf(ld - M) * inv;
    float4 tk = ((const float4*)(tokens + (size_t)t * E_DIM))[tid];
    float4 acc = make_float4(wdef * tk.x, wdef * tk.y, wdef * tk.z, wdef * tk.w);

    for (int base = 0; base < V_DIM; base += GCHUNK) {
        if (tid == 0) s_cnt = 0;
        __syncthreads();
        int end = min(base + GCHUNK, V_DIM);
        for (int i = base + tid; i < end; i += 256) {
            float l = row[i];
            if (l > cutoff) {
                int p = atomicAdd(&s_cnt, 1);
                s_idx[p] = i;
                s_w[p] = __expf(l - M) * inv;
            }
        }
        __syncthreads();
        int cnt = s_cnt;
        for (int p = 0; p < cnt; p++) {
            float w = s_w[p];
            float4 v = ((const float4*)(vocab + (size_t)s_idx[p] * E_DIM))[tid];
            acc.x += w * v.x; acc.y += w * v.y;
            acc.z += w * v.z; acc.w += w * v.w;
        }
        __syncthreads();
    }

    ((float4*)out)[(size_t)t * (E_DIM / 4) + tid] = acc;
}

// ===========================================================================
// Launch
// ===========================================================================
extern "C" void kernel_launch(void* const* d_in, const int* in_sizes, int n_in,
                              void* d_out, int out_size)
{
    const float* tokens = (const float*)d_in[0];   // [T, E]
    const float* vocab  = (const float*)d_in[1];   // [V, E]
    const float* weight = (const float*)d_in[2];   // [E, E]
    const float* dEmb   = (const float*)d_in[3];   // [E]
    float* out = (float*)d_out;

    float *X, *L, *Ld;
    __nv_bfloat16 *Xcat, *Vcat;
    cudaGetSymbolAddress((void**)&X,    g_X);
    cudaGetSymbolAddress((void**)&L,    g_L);
    cudaGetSymbolAddress((void**)&Ld,   g_Ld);
    cudaGetSymbolAddress((void**)&Xcat, g_Xcat);
    cudaGetSymbolAddress((void**)&Vcat, g_Vcat);

    // 1) vocab -> [hi|lo|hi] bf16 K-concat
    {
        int n4 = V_DIM * E_DIM / 4;
        split_cat_kernel<<<(n4 + 255) / 256, 256>>>(vocab, Vcat, n4, 1);
    }

    // 2) X = tokens @ W
    gemm_nn_kernel<<<dim3(E_DIM / BN, T_DIM / BM), 256>>>(
        tokens, weight, X, T_DIM, E_DIM, E_DIM);

    // 3) X -> [hi|hi|lo] bf16 K-concat
    {
        int n4 = T_DIM * E_DIM / 4;
        split_cat_kernel<<<(n4 + 255) / 256, 256>>>(X, Xcat, n4, 2);
    }

    // 4) Ld = X @ default_embedding
    dot_default_kernel<<<T_DIM / 8, 256>>>(X, dEmb, Ld);

    // 5) L = Xcat @ Vcat^T via mma.sync bf16 (3-term split folded into K)
    cudaFuncSetAttribute(mma_gemm_kernel,
                         cudaFuncAttributeMaxDynamicSharedMemorySize, GEMM_SMEM);
    mma_gemm_kernel<<<dim3(T_DIM / 128, (V_DIM + 127) / 128), 256, GEMM_SMEM>>>(
        Xcat, Vcat, L);

    // 6) softmax + sparse gather
    softmax_gather_kernel<<<T_DIM, 256>>>(L, Ld, tokens, vocab, out);
}

// round 8
// speedup vs baseline: 6.7276x; 2.3144x over previous
#include <cuda_runtime.h>
#include <cuda_bf16.h>
#include <math.h>
#include <stdint.h>

// Problem dims (fixed by the reference)
#define T_DIM 8192
#define E_DIM 1024
#define V_DIM 50000

// Scratch (allocation-free rule: __device__ globals)
__device__ float g_X[(size_t)T_DIM * E_DIM];                  // tokens @ W (32 MB)
__device__ float g_L[(size_t)T_DIM * V_DIM];                  // approx logits (1.64 GB)
__device__ float g_Ld[T_DIM];
__device__ __nv_bfloat16 g_Xh[(size_t)T_DIM * E_DIM];         // 16 MB
__device__ __nv_bfloat16 g_Vh[(size_t)V_DIM * E_DIM];         // 100 MB

// ===========================================================================
// PTX helpers (baseline sm_80+ features: compile clean for compute_103)
// ===========================================================================
__device__ __forceinline__ uint32_t smem_u32(const void* p) {
    uint32_t a;
    asm("{ .reg .u64 t; cvta.to.shared.u64 t, %1; cvt.u32.u64 %0, t; }"
        : "=r"(a) : "l"(p));
    return a;
}

__device__ __forceinline__ void cp16(uint32_t dst, const void* src, uint32_t sz) {
    asm volatile("cp.async.cg.shared.global [%0], [%1], 16, %2;"
                 :: "r"(dst), "l"(src), "r"(sz) : "memory");
}

__device__ __forceinline__ void ldsm_x4(uint32_t& r0, uint32_t& r1,
                                        uint32_t& r2, uint32_t& r3, uint32_t addr) {
    asm volatile("ldmatrix.sync.aligned.m8n8.x4.shared.b16 {%0,%1,%2,%3}, [%4];"
                 : "=r"(r0), "=r"(r1), "=r"(r2), "=r"(r3) : "r"(addr));
}

__device__ __forceinline__ void mma_bf16(float* c, const uint32_t* a,
                                         uint32_t b0, uint32_t b1) {
    asm volatile(
        "mma.sync.aligned.m16n8k16.row.col.f32.bf16.bf16.f32 "
        "{%0,%1,%2,%3}, {%4,%5,%6,%7}, {%8,%9}, {%0,%1,%2,%3};"
        : "+f"(c[0]), "+f"(c[1]), "+f"(c[2]), "+f"(c[3])
        : "r"(a[0]), "r"(a[1]), "r"(a[2]), "r"(a[3]), "r"(b0), "r"(b1));
}

__device__ __forceinline__ uint32_t swz(uint32_t o) { return o ^ ((o >> 3) & 0x70); }

// ===========================================================================
// fp32 -> bf16 (hi only), float4-vectorized
// ===========================================================================
__global__ void __launch_bounds__(256) split_hi_kernel(
    const float* __restrict__ src, __nv_bfloat16* __restrict__ dst, int n4)
{
    int i = blockIdx.x * 256 + threadIdx.x;
    if (i >= n4) return;
    float4 v = ((const float4*)src)[i];
    __nv_bfloat162* d = (__nv_bfloat162*)dst;
    d[2 * i]     = __nv_bfloat162(__float2bfloat16(v.x), __float2bfloat16(v.y));
    d[2 * i + 1] = __nv_bfloat162(__float2bfloat16(v.z), __float2bfloat16(v.w));
}

// ===========================================================================
// bf16 mma.sync GEMM:  L[T,V] = Xh[T,E] * Vh[V,E]^T   (hi-only, approx)
// CTA 128x128, BK=64, 8 warps (2x4) each 64x32, double-buffered cp.async
// ===========================================================================
#define GBK 64
#define KITERS (E_DIM / GBK)              // 16
#define STAGE_B 32768                     // A 16K + B 16K per stage
#define GEMM_SMEM (2 * STAGE_B)

__global__ void __launch_bounds__(256, 2) mma_gemm_kernel(
    const __nv_bfloat16* __restrict__ A, const __nv_bfloat16* __restrict__ B,
    float* __restrict__ C)
{
    extern __shared__ __align__(1024) char sm[];
    const uint32_t sbase = smem_u32(sm);
    const int tid  = threadIdx.x;
    const int lane = tid & 31;
    const int wid  = tid >> 5;
    const int bm = blockIdx.x * 128;
    const int bn = blockIdx.y * 128;
    const int wm = (wid >> 2) * 64;
    const int wn = (wid & 3) * 32;

    float acc[4][4][4];
#pragma unroll
    for (int mt = 0; mt < 4; mt++)
#pragma unroll
        for (int nt = 0; nt < 4; nt++)
#pragma unroll
            for (int r = 0; r < 4; r++) acc[mt][nt][r] = 0.f;

    auto load_stage = [&](int s, int k0) {
        uint32_t sa = sbase + s * STAGE_B;
#pragma unroll
        for (int r = 0; r < 4; ++r) {               // A: 128 rows x 128B
            int f = tid + r * 256;
            int row = f >> 3, q = f & 7;
            uint32_t so = swz((uint32_t)(row * 128 + q * 16));
            cp16(sa + so,
                 (const char*)(A + (size_t)(bm + row) * E_DIM + k0) + q * 16, 16u);
        }
#pragma unroll
        for (int r = 0; r < 4; ++r) {               // B: 128 rows x 128B (guard V)
            int f = tid + r * 256;
            int row = f >> 3, q = f & 7;
            int vr = bn + row;
            uint32_t so = swz((uint32_t)(row * 128 + q * 16));
            const char* src = (const char*)(
                B + (size_t)(vr < V_DIM ? vr : V_DIM - 1) * E_DIM + k0) + q * 16;
            cp16(sa + 16384 + so, src, vr < V_DIM ? 16u : 0u);
        }
    };

    load_stage(0, 0);
    asm volatile("cp.async.commit_group;" ::: "memory");

    for (int it = 0; it < KITERS; ++it) {
        if (it + 1 < KITERS) load_stage((it + 1) & 1, (it + 1) * GBK);
        asm volatile("cp.async.commit_group;" ::: "memory");
        asm volatile("cp.async.wait_group 1;" ::: "memory");
        __syncthreads();

        uint32_t sa = sbase + (it & 1) * STAGE_B;
        uint32_t sb = sa + 16384;
#pragma unroll
        for (int ks = 0; ks < 4; ++ks) {
            uint32_t a[4][4], b[2][4];
#pragma unroll
            for (int mt = 0; mt < 4; ++mt) {
                int row  = wm + mt * 16 + (lane & 15);
                int colb = ks * 32 + ((lane >> 4) << 4);
                ldsm_x4(a[mt][0], a[mt][1], a[mt][2], a[mt][3],
                        sa + swz((uint32_t)(row * 128 + colb)));
            }
#pragma unroll
            for (int np = 0; np < 2; ++np) {
                int nrow = wn + np * 16 + ((lane >> 4) << 3) + (lane & 7);
                int colb = ks * 32 + (((lane >> 3) & 1) << 4);
                ldsm_x4(b[np][0], b[np][1], b[np][2], b[np][3],
                        sb + swz((uint32_t)(nrow * 128 + colb)));
            }
#pragma unroll
            for (int mt = 0; mt < 4; ++mt)
#pragma unroll
                for (int nt = 0; nt < 4; ++nt)
                    mma_bf16(acc[mt][nt], a[mt],
                             b[nt >> 1][(nt & 1) * 2], b[nt >> 1][(nt & 1) * 2 + 1]);
        }
        __syncthreads();
    }

#pragma unroll
    for (int mt = 0; mt < 4; ++mt) {
        int row = bm + wm + mt * 16 + (lane >> 2);
        float* r0 = C + (size_t)row * V_DIM;
        float* r1 = C + (size_t)(row + 8) * V_DIM;
#pragma unroll
        for (int nt = 0; nt < 4; ++nt) {
            int col = bn + wn + nt * 8 + ((lane & 3) << 1);
            if (col < V_DIM) {
                *(float2*)(r0 + col) = make_float2(acc[mt][nt][0], acc[mt][nt][1]);
                *(float2*)(r1 + col) = make_float2(acc[mt][nt][2], acc[mt][nt][3]);
            }
        }
    }
}

// ===========================================================================
// fp32 NN GEMM for X = tokens @ W  (exact fp32; X feeds candidate recompute)
// ===========================================================================
#define BM 128
#define BN 128
#define BK 16
#define TM 8
#define TN 8
#define SPAD 4

__global__ void __launch_bounds__(256) gemm_nn_kernel(
    const float* __restrict__ A, const float* __restrict__ B,
    float* __restrict__ C, int M, int N, int K)
{
    __shared__ float As[BK][BM + SPAD];
    __shared__ float Bs[BK][BN + SPAD];
    const int tid = threadIdx.x;
    const int bm = blockIdx.y * BM;
    const int bn = blockIdx.x * BN;
    const int tx = tid & 15;
    const int ty = tid >> 4;

    float acc[TM][TN];
#pragma unroll
    for (int i = 0; i < TM; i++)
#pragma unroll
        for (int j = 0; j < TN; j++) acc[i][j] = 0.f;

    for (int k0 = 0; k0 < K; k0 += BK) {
#pragma unroll
        for (int r = 0; r < 2; r++) {
            int f = tid + r * 256;
            int row = f >> 2;
            int kq = (f & 3) * 4;
            float4 v = *(const float4*)&A[(size_t)(bm + row) * K + k0 + kq];
            As[kq + 0][row] = v.x; As[kq + 1][row] = v.y;
            As[kq + 2][row] = v.z; As[kq + 3][row] = v.w;
        }
#pragma unroll
        for (int r = 0; r < 2; r++) {
            int f = tid + r * 256;
            int kr = f >> 5;
            int nq = (f & 31) * 4;
            float4 v = *(const float4*)&B[(size_t)(k0 + kr) * N + bn + nq];
            Bs[kr][nq + 0] = v.x; Bs[kr][nq + 1] = v.y;
            Bs[kr][nq + 2] = v.z; Bs[kr][nq + 3] = v.w;
        }
        __syncthreads();
#pragma unroll
        for (int kk = 0; kk < BK; kk++) {
            float a[TM], b[TN];
#pragma unroll
            for (int i = 0; i < TM; i++) a[i] = As[kk][ty * TM + i];
#pragma unroll
            for (int j = 0; j < TN; j++) b[j] = Bs[kk][tx * TN + j];
#pragma unroll
            for (int i = 0; i < TM; i++)
#pragma unroll
                for (int j = 0; j < TN; j++) acc[i][j] += a[i] * b[j];
        }
        __syncthreads();
    }
#pragma unroll
    for (int i = 0; i < TM; i++) {
        int gm = bm + ty * TM + i;
#pragma unroll
        for (int j = 0; j < TN; j++)
            C[(size_t)gm * N + bn + tx * TN + j] = acc[i][j];
    }
}

// ===========================================================================
// Ld[t] = dot(X[t,:], default_embedding)   (exact fp32)
// ===========================================================================
__global__ void __launch_bounds__(256) dot_default_kernel(
    const float* __restrict__ X, const float* __restrict__ d,
    float* __restrict__ Ld)
{
    int w = threadIdx.x >> 5;
    int lane = threadIdx.x & 31;
    int t = blockIdx.x * 8 + w;
    const float4* xr = (const float4*)(X + (size_t)t * E_DIM);
    const float4* dr = (const float4*)d;
    float s = 0.f;
    for (int q = lane; q < E_DIM / 4; q += 32) {
        float4 a = xr[q], b = dr[q];
        s += a.x * b.x + a.y * b.y + a.z * b.z + a.w * b.w;
    }
#pragma unroll
    for (int o = 16; o; o >>= 1) s += __shfl_xor_sync(0xffffffffu, s, o);
    if (lane == 0) Ld[t] = s;
}

// ===========================================================================
// Softmax over approx logits -> candidate set -> EXACT fp32 recompute of
// candidate logits -> exact weights -> sparse gather.
//   weight > 1e-9 cutoff, widened by 1.0 margin for bf16 logit error (~0.04)
// ===========================================================================
#define CAND_MAX 256
#define NWLOG    20.72f     // -ln(1e-9)
#define MARGIN   1.0f

__global__ void __launch_bounds__(256) softmax_gather_kernel(
    const float* __restrict__ L, const float* __restrict__ Ld,
    const float* __restrict__ tokens, const float* __restrict__ vocab,
    const float* __restrict__ X, float* __restrict__ out)
{
    const int t = blockIdx.x;
    const int tid = threadIdx.x;
    const int lane = tid & 31;
    const int wid = tid >> 5;
    const float4* row4 = (const float4*)(L + (size_t)t * V_DIM);

    __shared__ float rm[256], rz[256];
    __shared__ int   s_idx[CAND_MAX];
    __shared__ float s_dot[CAND_MAX];
    __shared__ float s_part[CAND_MAX][8];
    __shared__ int   s_cnt;
    __shared__ __align__(16) float sX[E_DIM];   // float4-accessed: force alignment
    __shared__ float s_M, s_invZ;

    // X row -> shared (exact fp32)
    ((float4*)sX)[tid] = ((const float4*)(X + (size_t)t * E_DIM))[tid];
    if (tid == 0) s_cnt = 0;

    const float ld = Ld[t];

    // ---- pass 1: online max+sum over approx logits (float4) ----
    float m = -3.0e38f, z = 0.f;
    for (int i = tid; i < V_DIM / 4; i += 256) {
        float4 v = row4[i];
        float ml = fmaxf(fmaxf(v.x, v.y), fmaxf(v.z, v.w));
        if (ml > m) { z *= __expf(m - ml); m = ml; }
        z += __expf(v.x - m) + __expf(v.y - m) + __expf(v.z - m) + __expf(v.w - m);
    }
    if (tid == 0) {
        if (ld > m) { z = z * __expf(m - ld) + 1.f; m = ld; }
        else z += __expf(ld - m);
    }
    rm[tid] = m; rz[tid] = z; __syncthreads();
    for (int s = 128; s > 0; s >>= 1) {
        if (tid < s) {
            float m2 = rm[tid + s], z2 = rz[tid + s];
            float M = fmaxf(rm[tid], m2);
            rz[tid] = rz[tid] * __expf(rm[tid] - M) + z2 * __expf(m2 - M);
            rm[tid] = M;
        }
        __syncthreads();
    }
    const float Ma = rm[0];
    const float cutoff = Ma + logf(rz[0]) - NWLOG - MARGIN;
    __syncthreads();

    // ---- pass 2: collect candidate indices (L2-hot reread) ----
    for (int i = tid; i < V_DIM / 4; i += 256) {
        float4 v = row4[i];
        if (v.x > cutoff) { int p = atomicAdd(&s_cnt, 1); if (p < CAND_MAX) s_idx[p] = 4 * i; }
        if (v.y > cutoff) { int p = atomicAdd(&s_cnt, 1); if (p < CAND_MAX) s_idx[p] = 4 * i + 1; }
        if (v.z > cutoff) { int p = atomicAdd(&s_cnt, 1); if (p < CAND_MAX) s_idx[p] = 4 * i + 2; }
        if (v.w > cutoff) { int p = atomicAdd(&s_cnt, 1); if (p < CAND_MAX) s_idx[p] = 4 * i + 3; }
    }
    __syncthreads();
    const int cnt = min(s_cnt, CAND_MAX);

    // ---- exact fp32 dots for candidates (deterministic warp-split reduce) ----
    {
        float4 x = ((const float4*)sX)[wid * 32 + lane];   // warp w owns cols [128w,128(w+1))
        for (int p = 0; p < cnt; ++p) {
            const float4* vr = (const float4*)(vocab + (size_t)s_idx[p] * E_DIM);
            float4 v = vr[wid * 32 + lane];
            float s = x.x * v.x + x.y * v.y + x.z * v.z + x.w * v.w;
#pragma unroll
            for (int o = 16; o; o >>= 1) s += __shfl_xor_sync(0xffffffffu, s, o);
            if (lane == 0) s_part[p][wid] = s;
        }
    }
    __syncthreads();
    if (tid < cnt) {
        float d = 0.f;
#pragma unroll
        for (int w = 0; w < 8; ++w) d += s_part[tid][w];
        s_dot[tid] = d;
    }
    __syncthreads();

    // ---- exact max / Z over candidates + default key ----
    if (tid == 0) {
        float Mex = ld;
        for (int p = 0; p < cnt; ++p) Mex = fmaxf(Mex, s_dot[p]);
        float Z = __expf(ld - Mex);
        for (int p = 0; p < cnt; ++p) Z += __expf(s_dot[p] - Mex);
        s_M = Mex; s_invZ = 1.0f / Z;
    }
    __syncthreads();
    const float Mex = s_M, invZ = s_invZ;

    // ---- weighted accumulation (thread owns 4 output cols) ----
    const float wdef = __expf(ld - Mex) * invZ;
    float4 tk = ((const float4*)(tokens + (size_t)t * E_DIM))[tid];
    float4 acc = make_float4(wdef * tk.x, wdef * tk.y, wdef * tk.z, wdef * tk.w);

    for (int p = 0; p < cnt; ++p) {
        float w = __expf(s_dot[p] - Mex) * invZ;
        float4 v = ((const float4*)(vocab + (size_t)s_idx[p] * E_DIM))[tid];
        acc.x += w * v.x; acc.y += w * v.y;
        acc.z += w * v.z; acc.w += w * v.w;
    }

    ((float4*)out)[(size_t)t * (E_DIM / 4) + tid] = acc;
}

// ===========================================================================
// Launch
// ===========================================================================
extern "C" void kernel_launch(void* const* d_in, const int* in_sizes, int n_in,
                              void* d_out, int out_size)
{
    const float* tokens = (const float*)d_in[0];   // [T, E]
    const float* vocab  = (const float*)d_in[1];   // [V, E]
    const float* weight = (const float*)d_in[2];   // [E, E]
    const float* dEmb   = (const float*)d_in[3];   // [E]
    float* out = (float*)d_out;

    float *X, *L, *Ld;
    __nv_bfloat16 *Xh, *Vh;
    cudaGetSymbolAddress((void**)&X,  g_X);
    cudaGetSymbolAddress((void**)&L,  g_L);
    cudaGetSymbolAddress((void**)&Ld, g_Ld);
    cudaGetSymbolAddress((void**)&Xh, g_Xh);
    cudaGetSymbolAddress((void**)&Vh, g_Vh);

    // 1) vocab -> bf16 hi
    {
        int n4 = V_DIM * E_DIM / 4;
        split_hi_kernel<<<(n4 + 255) / 256, 256>>>(vocab, Vh, n4);
    }

    // 2) X = tokens @ W  (exact fp32)
    gemm_nn_kernel<<<dim3(E_DIM / BN, T_DIM / BM), 256>>>(
        tokens, weight, X, T_DIM, E_DIM, E_DIM);

    // 3) X -> bf16 hi
    {
        int n4 = T_DIM * E_DIM / 4;
        split_hi_kernel<<<(n4 + 255) / 256, 256>>>(X, Xh, n4);
    }

    // 4) Ld = X @ default_embedding  (exact fp32)
    dot_default_kernel<<<T_DIM / 8, 256>>>(X, dEmb, Ld);

    // 5) approx logits L = Xh @ Vh^T  (hi-only bf16 mma.sync)
    cudaFuncSetAttribute(mma_gemm_kernel,
                         cudaFuncAttributeMaxDynamicSharedMemorySize, GEMM_SMEM);
    mma_gemm_kernel<<<dim3(T_DIM / 128, (V_DIM + 127) / 128), 256, GEMM_SMEM>>>(
        Xh, Vh, L);

    // 6) softmax w/ exact candidate recompute + sparse gather
    softmax_gather_kernel<<<T_DIM, 256>>>(L, Ld, tokens, vocab, X, out);
}